// round 4
// baseline (speedup 1.0000x reference)
#include <cuda_runtime.h>

#define HW 256
#define NB 128
#define NCLUST 64
#define PAD 257
#define NTHREADS 256

// Scratch: complex spectrum in TRANSPOSED layout [b][w][h]. 64 MB static device array
// (allowed workaround for the no-alloc rule).
__device__ float2 g_scratch[(size_t)NB * HW * HW];

// Shared memory layout: [0..255] twiddle table, [256 .. 256+32*PAD) data tile,
// then 64 floats of pattern_importance row (kernel 2 only).
#define SMEM_BYTES ((256 + 32 * PAD) * (int)sizeof(float2) + 64 * (int)sizeof(float))

__device__ __forceinline__ void build_tw(float2* tw, int tid) {
    if (tid < 256) {
        float s, c;
        // W^t = exp(-2*pi*i*t/256) = exp(-i*pi*t/128)
        sincospif(-(float)tid * (1.0f / 128.0f), &s, &c);
        tw[tid] = make_float2(c, s);
    }
}

// Forward radix-2 DIF FFT-256 on one smem row; natural input -> bit-reversed output.
// Executed cooperatively by one full warp (4 butterflies per lane per stage).
__device__ __forceinline__ void fft_dif_row(float2* row, const float2* tw, int lane) {
#pragma unroll
    for (int s = 0; s < 8; ++s) {
        const int span = 128 >> s;
#pragma unroll
        for (int k = 0; k < 4; ++k) {
            int m = lane + (k << 5);
            int j = m & (span - 1);
            int i0 = ((m & ~(span - 1)) << 1) | j;
            int i1 = i0 + span;
            float2 a = row[i0];
            float2 b = row[i1];
            row[i0] = make_float2(a.x + b.x, a.y + b.y);
            float dx = a.x - b.x, dy = a.y - b.y;
            float2 w = tw[j << s];
            row[i1] = make_float2(dx * w.x - dy * w.y, dx * w.y + dy * w.x);
        }
        __syncwarp();
    }
}

// Inverse (unnormalized) radix-2 DIT FFT-256; bit-reversed input -> natural output.
__device__ __forceinline__ void ifft_dit_row(float2* row, const float2* tw, int lane) {
#pragma unroll
    for (int s = 0; s < 8; ++s) {
        const int span = 1 << s;
#pragma unroll
        for (int k = 0; k < 4; ++k) {
            int m = lane + (k << 5);
            int j = m & (span - 1);
            int i0 = ((m & ~(span - 1)) << 1) | j;
            int i1 = i0 + span;
            float2 w = tw[j << (7 - s)];  // conjugated below
            float2 a = row[i0];
            float2 b = row[i1];
            float tx = b.x * w.x + b.y * w.y;   // b * conj(w)
            float ty = b.y * w.x - b.x * w.y;
            row[i0] = make_float2(a.x + tx, a.y + ty);
            row[i1] = make_float2(a.x - tx, a.y - ty);
        }
        __syncwarp();
    }
}

// Kernel 1: row forward FFT; write scratch transposed [b][w][h].
__global__ void k_rowfft(const float* __restrict__ x) {
    extern __shared__ float2 smem[];
    float2* tw = smem;
    float2* tile = smem + 256;
    int tid = threadIdx.x;
    int b = blockIdx.x >> 3;
    int h0 = (blockIdx.x & 7) << 5;
    build_tw(tw, tid);
    const float* xb = x + (size_t)(b * HW + h0) * HW;
    for (int idx = tid; idx < 32 * HW; idx += NTHREADS) {
        int r = idx >> 8, w = idx & 255;
        tile[r * PAD + w] = make_float2(xb[idx], 0.0f);
    }
    __syncthreads();
    int warp = tid >> 5, lane = tid & 31;
#pragma unroll
    for (int r4 = 0; r4 < 4; ++r4)
        fft_dif_row(tile + (warp * 4 + r4) * PAD, tw, lane);
    __syncthreads();
    float2* sb = g_scratch + (size_t)b * HW * HW + h0;
    for (int idx = tid; idx < 32 * HW; idx += NTHREADS) {
        int r = idx & 31, w = idx >> 5;          // coalesced 256B global chunks
        sb[(size_t)w * HW + r] = tile[r * PAD + w];
    }
}

// Kernel 2: column forward FFT + mask multiply (bit-reversed domain) + column inverse FFT.
__global__ void k_colfft_mask(const float* __restrict__ pi, const int* __restrict__ cid) {
    extern __shared__ float2 smem[];
    float2* tw = smem;
    float2* tile = smem + 256;
    float* spi = (float*)(tile + 32 * PAD);
    int tid = threadIdx.x;
    int b = blockIdx.x >> 3;
    int w0 = (blockIdx.x & 7) << 5;
    build_tw(tw, tid);
    int p = b ^ 64;                              // batch fftshift -> importance row permutation
    if (tid < 64) spi[tid] = pi[p * 64 + tid];
    float2* sb = g_scratch + (size_t)(b * HW + w0) * HW;
    for (int idx = tid; idx < 32 * HW; idx += NTHREADS)
        tile[(idx >> 8) * PAD + (idx & 255)] = sb[idx];
    __syncthreads();
    int warp = tid >> 5, lane = tid & 31;
#pragma unroll
    for (int r4 = 0; r4 < 4; ++r4)
        fft_dif_row(tile + (warp * 4 + r4) * PAD, tw, lane);
    __syncthreads();
    // Mask in bit-reversed (hp) x bit-reversed (w, from kernel1) domain.
    for (int idx = tid; idx < 32 * HW; idx += NTHREADS) {
        int j = idx >> 8, hp = idx & 255;
        int wl = __brev(w0 + j) >> 24;
        int hl = __brev(hp) >> 24;
        int hs = hl ^ 128, ws = wl ^ 128;        // spatial fftshift of the mask
        int c = __ldg(&cid[hs * HW + ws]);
        float m = (c < NCLUST) ? spi[c] : 1.0f;
        float2 v = tile[j * PAD + hp];
        tile[j * PAD + hp] = make_float2(v.x * m, v.y * m);
    }
    __syncthreads();
#pragma unroll
    for (int r4 = 0; r4 < 4; ++r4)
        ifft_dit_row(tile + (warp * 4 + r4) * PAD, tw, lane);
    __syncthreads();
    for (int idx = tid; idx < 32 * HW; idx += NTHREADS)
        sb[idx] = tile[(idx >> 8) * PAD + (idx & 255)];
}

// Kernel 3: row inverse FFT + normalize + magnitude + emit [x, x_ifft, |x_ifft-x|].
__global__ void k_rowifft_out(const float* __restrict__ x, float* __restrict__ out) {
    extern __shared__ float2 smem[];
    float2* tw = smem;
    float2* tile = smem + 256;
    int tid = threadIdx.x;
    int b = blockIdx.x >> 3;
    int h0 = (blockIdx.x & 7) << 5;
    build_tw(tw, tid);
    float2* sb = g_scratch + (size_t)b * HW * HW + h0;
    for (int idx = tid; idx < 32 * HW; idx += NTHREADS) {
        int r = idx & 31, w = idx >> 5;
        tile[r * PAD + w] = sb[(size_t)w * HW + r];
    }
    __syncthreads();
    int warp = tid >> 5, lane = tid & 31;
#pragma unroll
    for (int r4 = 0; r4 < 4; ++r4)
        ifft_dit_row(tile + (warp * 4 + r4) * PAD, tw, lane);
    __syncthreads();
    const float* xb = x + (size_t)(b * HW + h0) * HW;
    float* o0 = out + ((size_t)(b * 3 + 0) * HW + h0) * HW;
    float* o1 = out + ((size_t)(b * 3 + 1) * HW + h0) * HW;
    float* o2 = out + ((size_t)(b * 3 + 2) * HW + h0) * HW;
    const float inv = 1.0f / 65536.0f;           // ifft2 normalization (both axes)
    for (int idx = tid; idx < 32 * HW; idx += NTHREADS) {
        int r = idx >> 8, w = idx & 255;
        float2 z = tile[r * PAD + w];
        float mag = sqrtf(z.x * z.x + z.y * z.y) * inv;
        float xv = xb[idx];
        o0[idx] = xv;
        o1[idx] = mag;
        o2[idx] = fabsf(mag - xv);
    }
}

extern "C" void kernel_launch(void* const* d_in, const int* in_sizes, int n_in,
                              void* d_out, int out_size) {
    (void)in_sizes; (void)n_in;
    const float* x   = (const float*)d_in[0];
    const float* pi  = (const float*)d_in[1];
    const int*   cid = (const int*)d_in[2];
    float* out = (float*)d_out;

    cudaFuncSetAttribute(k_rowfft,      cudaFuncAttributeMaxDynamicSharedMemorySize, SMEM_BYTES);
    cudaFuncSetAttribute(k_colfft_mask, cudaFuncAttributeMaxDynamicSharedMemorySize, SMEM_BYTES);
    cudaFuncSetAttribute(k_rowifft_out, cudaFuncAttributeMaxDynamicSharedMemorySize, SMEM_BYTES);

    dim3 grid(NB * 8);
    k_rowfft<<<grid, NTHREADS, SMEM_BYTES>>>(x);
    k_colfft_mask<<<grid, NTHREADS, SMEM_BYTES>>>(pi, cid);
    k_rowifft_out<<<grid, NTHREADS, SMEM_BYTES>>>(x, out);

    // Second tuple element: pattern_importance passthrough, appended after x_new.
    const long long XN = (long long)NB * 3 * HW * HW;  // 25,165,824
    if ((long long)out_size >= XN + (long long)NB * NCLUST) {
        cudaMemcpyAsync(out + XN, pi, (size_t)NB * NCLUST * sizeof(float),
                        cudaMemcpyDeviceToDevice);
    }
}

// round 5
// speedup vs baseline: 2.2557x; 2.2557x over previous
#include <cuda_runtime.h>

#define HW 256
#define NB 128
#define NCLUST 64
#define NTHREADS 256
#define PAD2 257
#define FULLM 0xffffffffu

// Scratch spectrum, transposed layout [b][w][h].
__device__ float2 g_scratch[(size_t)NB * HW * HW];
// Pre-permuted cluster ids: cidP[wp*256+m] = cid[rev8(m)^128][rev8(wp)^128], -1 if unassigned.
__device__ int g_cidP[HW * HW];

__device__ __forceinline__ float2 cmul(float2 a, float2 b) {
    return make_float2(a.x * b.x - a.y * b.y, a.x * b.y + a.y * b.x);
}
__device__ __forceinline__ float2 cmulc(float2 a, float2 b) {  // a * conj(b)
    return make_float2(a.x * b.x + a.y * b.y, a.y * b.x - a.x * b.y);
}

struct Tw {
    float2 T0[4];                 // span-128 twiddles: W^l * W8^k
    float2 W2, W2i, W4;           // span-64 (and -i variant), span-32
    float2 C16, C8, C4, C2;       // cross-stage selects (identity on lower lanes)
    float sg16, sg8, sg4, sg2, sg1;
};

__device__ __forceinline__ void make_tw(Tw& t, int l) {
    float s, c;
    sincospif(-(float)l * (1.0f / 128.0f), &s, &c);      // W_256^l
    float2 Wl = make_float2(c, s);
    const float s2 = 0.70710678118654752440f;
    t.T0[0] = Wl;                                        // * W8^0
    t.T0[1] = make_float2(s2 * (Wl.x + Wl.y), s2 * (Wl.y - Wl.x));   // * W8^1
    t.T0[2] = make_float2(Wl.y, -Wl.x);                  // * -i
    t.T0[3] = make_float2(s2 * (Wl.y - Wl.x), -s2 * (Wl.x + Wl.y));  // * W8^3
    t.W2  = cmul(Wl, Wl);                                // W^{2l}
    t.W2i = make_float2(t.W2.y, -t.W2.x);                // -i * W^{2l}
    t.W4  = cmul(t.W2, t.W2);                            // W^{4l}
    if (l & 16) { sincospif(-(float)(l & 15) * (1.0f / 16.0f), &s, &c); t.C16 = make_float2(c, s); }
    else t.C16 = make_float2(1.f, 0.f);
    if (l & 8)  { sincospif(-(float)(l & 7) * (1.0f / 8.0f), &s, &c);  t.C8 = make_float2(c, s); }
    else t.C8 = make_float2(1.f, 0.f);
    if (l & 4)  { sincospif(-(float)(l & 3) * (1.0f / 4.0f), &s, &c);  t.C4 = make_float2(c, s); }
    else t.C4 = make_float2(1.f, 0.f);
    t.C2 = ((l & 3) == 3) ? make_float2(0.f, -1.f) : make_float2(1.f, 0.f);
    t.sg16 = (l & 16) ? -1.f : 1.f;
    t.sg8  = (l & 8)  ? -1.f : 1.f;
    t.sg4  = (l & 4)  ? -1.f : 1.f;
    t.sg2  = (l & 2)  ? -1.f : 1.f;
    t.sg1  = (l & 1)  ? -1.f : 1.f;
}

// DIF local butterfly: (a,b) -> (a+b, (a-b)*W)
#define BF_F(A, B, W) do { float2 _a = (A), _b = (B); \
    (A) = make_float2(_a.x + _b.x, _a.y + _b.y); \
    (B) = cmul(make_float2(_a.x - _b.x, _a.y - _b.y), (W)); } while (0)
// DIT local butterfly with conj twiddle: t = b*conj(W); (a,b) -> (a+t, a-t)
#define BF_I(A, B, W) do { float2 _t = cmulc((B), (W)); float2 _a = (A); \
    (A) = make_float2(_a.x + _t.x, _a.y + _t.y); \
    (B) = make_float2(_a.x - _t.x, _a.y - _t.y); } while (0)

__device__ __forceinline__ void cross_f(float2 r[8], int S, float sg, float2 C) {
#pragma unroll
    for (int k = 0; k < 8; ++k) {
        float vx = __shfl_xor_sync(FULLM, r[k].x, S);
        float vy = __shfl_xor_sync(FULLM, r[k].y, S);
        float2 u = make_float2(fmaf(sg, r[k].x, vx), fmaf(sg, r[k].y, vy));
        r[k] = cmul(u, C);
    }
}
__device__ __forceinline__ void cross_i(float2 r[8], int S, float sg, float2 C) {
#pragma unroll
    for (int k = 0; k < 8; ++k) {
        float2 y = cmulc(r[k], C);  // identity on lower lanes (C=1)
        float vx = __shfl_xor_sync(FULLM, y.x, S);
        float vy = __shfl_xor_sync(FULLM, y.y, S);
        r[k] = make_float2(fmaf(sg, y.x, vx), fmaf(sg, y.y, vy));
    }
}

// Forward DIF FFT-256: natural order in (reg k of lane l = index 32k+l),
// bit-reversed-bin order out at the same in-place indices.
__device__ __forceinline__ void fwd256(float2 r[8], const Tw& t) {
#pragma unroll
    for (int k = 0; k < 4; ++k) BF_F(r[k], r[k + 4], t.T0[k]);         // span 128
    BF_F(r[0], r[2], t.W2);  BF_F(r[1], r[3], t.W2i);                  // span 64
    BF_F(r[4], r[6], t.W2);  BF_F(r[5], r[7], t.W2i);
    BF_F(r[0], r[1], t.W4);  BF_F(r[2], r[3], t.W4);                   // span 32
    BF_F(r[4], r[5], t.W4);  BF_F(r[6], r[7], t.W4);
    cross_f(r, 16, t.sg16, t.C16);
    cross_f(r, 8,  t.sg8,  t.C8);
    cross_f(r, 4,  t.sg4,  t.C4);
    cross_f(r, 2,  t.sg2,  t.C2);
#pragma unroll
    for (int k = 0; k < 8; ++k) {                                      // span 1, W=1
        float vx = __shfl_xor_sync(FULLM, r[k].x, 1);
        float vy = __shfl_xor_sync(FULLM, r[k].y, 1);
        r[k] = make_float2(fmaf(t.sg1, r[k].x, vx), fmaf(t.sg1, r[k].y, vy));
    }
}

// Inverse (unnormalized, x256) DIT FFT-256: bit-reversed bins in -> natural out.
__device__ __forceinline__ void inv256(float2 r[8], const Tw& t) {
#pragma unroll
    for (int k = 0; k < 8; ++k) {                                      // span 1
        float vx = __shfl_xor_sync(FULLM, r[k].x, 1);
        float vy = __shfl_xor_sync(FULLM, r[k].y, 1);
        r[k] = make_float2(fmaf(t.sg1, r[k].x, vx), fmaf(t.sg1, r[k].y, vy));
    }
    cross_i(r, 2,  t.sg2,  t.C2);
    cross_i(r, 4,  t.sg4,  t.C4);
    cross_i(r, 8,  t.sg8,  t.C8);
    cross_i(r, 16, t.sg16, t.C16);
    BF_I(r[0], r[1], t.W4);  BF_I(r[2], r[3], t.W4);                   // span 32
    BF_I(r[4], r[5], t.W4);  BF_I(r[6], r[7], t.W4);
    BF_I(r[0], r[2], t.W2);  BF_I(r[1], r[3], t.W2i);                  // span 64
    BF_I(r[4], r[6], t.W2);  BF_I(r[5], r[7], t.W2i);
#pragma unroll
    for (int k = 0; k < 4; ++k) BF_I(r[k], r[k + 4], t.T0[k]);         // span 128
}

// Prep: pre-permute cluster map into the k2 access order.
__global__ void k_prep(const int* __restrict__ cid) {
    int idx = blockIdx.x * NTHREADS + threadIdx.x;   // 0..65535
    int wp = idx >> 8, m = idx & 255;
    int hs = (__brev(m)  >> 24) ^ 128;
    int ws = (__brev(wp) >> 24) ^ 128;
    int c = cid[hs * HW + ws];
    g_cidP[idx] = (c < NCLUST) ? c : -1;
}

// Kernel 1: row forward FFT (register/shuffle), write scratch transposed [b][w][h].
__global__ void k_rowfft(const float* __restrict__ x) {
    extern __shared__ float2 tile[];     // [32][PAD2]
    int tid = threadIdx.x, lane = tid & 31, warp = tid >> 5;
    int b = blockIdx.x >> 3, h0 = (blockIdx.x & 7) << 5;
    Tw t; make_tw(t, lane);
#pragma unroll
    for (int rr = 0; rr < 4; ++rr) {
        int row = warp * 4 + rr;
        const float* xr = x + (size_t)(b * HW + h0 + row) * HW;
        float2 r[8];
#pragma unroll
        for (int k = 0; k < 8; ++k) r[k] = make_float2(xr[32 * k + lane], 0.f);
        fwd256(r, t);
        float2* trow = tile + row * PAD2;
#pragma unroll
        for (int k = 0; k < 8; ++k) trow[32 * k + lane] = r[k];
    }
    __syncthreads();
    float2* sb = g_scratch + (size_t)b * HW * HW + h0;
    for (int idx = tid; idx < 32 * HW; idx += NTHREADS) {
        int rr = idx & 31, w = idx >> 5;             // 256B coalesced global chunks
        sb[(size_t)w * HW + rr] = tile[rr * PAD2 + w];
    }
}

// Kernel 2: column fwd FFT + mask (bit-reversed domain, pre-permuted cid) + column inv FFT.
// No smem tile needed: h-lines are contiguous in scratch.
__global__ void k_colfft_mask(const float* __restrict__ pi) {
    __shared__ float spi[NCLUST];
    int tid = threadIdx.x, lane = tid & 31, warp = tid >> 5;
    int b = blockIdx.x >> 3, wp0 = (blockIdx.x & 7) << 5;
    if (tid < NCLUST) spi[tid] = pi[(b ^ 64) * NCLUST + tid];   // batch fftshift
    Tw t; make_tw(t, lane);
    __syncthreads();
#pragma unroll
    for (int rr = 0; rr < 4; ++rr) {
        int wp = wp0 + warp * 4 + rr;
        float2* line = g_scratch + (size_t)(b * HW + wp) * HW;
        const int* cp = g_cidP + wp * HW;
        float2 r[8];
#pragma unroll
        for (int k = 0; k < 8; ++k) r[k] = line[32 * k + lane];
        fwd256(r, t);
#pragma unroll
        for (int k = 0; k < 8; ++k) {
            int c = __ldg(&cp[32 * k + lane]);       // coalesced
            float m = (c >= 0) ? spi[c] : 1.0f;
            r[k].x *= m; r[k].y *= m;
        }
        inv256(r, t);
#pragma unroll
        for (int k = 0; k < 8; ++k) line[32 * k + lane] = r[k];
    }
}

// Kernel 3: row inverse FFT + normalize + magnitude + emit [x, x_ifft, |x_ifft-x|].
__global__ void k_rowifft_out(const float* __restrict__ x, float* __restrict__ out) {
    extern __shared__ float2 tile[];
    int tid = threadIdx.x, lane = tid & 31, warp = tid >> 5;
    int b = blockIdx.x >> 3, h0 = (blockIdx.x & 7) << 5;
    Tw t; make_tw(t, lane);
    float2* sb = g_scratch + (size_t)b * HW * HW + h0;
    for (int idx = tid; idx < 32 * HW; idx += NTHREADS) {
        int rr = idx & 31, w = idx >> 5;             // coalesced global reads
        tile[rr * PAD2 + w] = sb[(size_t)w * HW + rr];
    }
    __syncthreads();
    const float inv = 1.0f / 65536.0f;
#pragma unroll
    for (int rr = 0; rr < 4; ++rr) {
        int row = warp * 4 + rr;
        float2 r[8];
        float2* trow = tile + row * PAD2;
#pragma unroll
        for (int k = 0; k < 8; ++k) r[k] = trow[32 * k + lane];
        inv256(r, t);
        int h = h0 + row;
        const float* xr = x + (size_t)(b * HW + h) * HW;
        float* o0 = out + ((size_t)(b * 3 + 0) * HW + h) * HW;
        float* o1 = out + ((size_t)(b * 3 + 1) * HW + h) * HW;
        float* o2 = out + ((size_t)(b * 3 + 2) * HW + h) * HW;
#pragma unroll
        for (int k = 0; k < 8; ++k) {
            int idx = 32 * k + lane;
            float2 z = r[k];
            float mag = sqrtf(z.x * z.x + z.y * z.y) * inv;
            float xv = xr[idx];
            o0[idx] = xv;
            o1[idx] = mag;
            o2[idx] = fabsf(mag - xv);
        }
    }
}

#define TILE_BYTES (32 * PAD2 * (int)sizeof(float2))

extern "C" void kernel_launch(void* const* d_in, const int* in_sizes, int n_in,
                              void* d_out, int out_size) {
    (void)in_sizes; (void)n_in;
    const float* x   = (const float*)d_in[0];
    const float* pi  = (const float*)d_in[1];
    const int*   cid = (const int*)d_in[2];
    float* out = (float*)d_out;

    cudaFuncSetAttribute(k_rowfft,      cudaFuncAttributeMaxDynamicSharedMemorySize, TILE_BYTES);
    cudaFuncSetAttribute(k_rowifft_out, cudaFuncAttributeMaxDynamicSharedMemorySize, TILE_BYTES);

    k_prep<<<HW, NTHREADS>>>(cid);
    k_rowfft<<<NB * 8, NTHREADS, TILE_BYTES>>>(x);
    k_colfft_mask<<<NB * 8, NTHREADS>>>(pi);
    k_rowifft_out<<<NB * 8, NTHREADS, TILE_BYTES>>>(x, out);

    // Second tuple element: pattern_importance passthrough, appended after x_new.
    const long long XN = (long long)NB * 3 * HW * HW;
    if ((long long)out_size >= XN + (long long)NB * NCLUST) {
        cudaMemcpyAsync(out + XN, pi, (size_t)NB * NCLUST * sizeof(float),
                        cudaMemcpyDeviceToDevice);
    }
}

// round 7
// speedup vs baseline: 2.9818x; 1.3219x over previous
#include <cuda_runtime.h>

#define HW 256
#define NB 128
#define NCLUST 64
#define NTHREADS 256
#define PAD2 257
#define FULLM 0xffffffffu

// Scratch A: spectrum after row FFT, transposed layout [b][w][h].
__device__ float2 g_scratch[(size_t)NB * HW * HW];
// Scratch B: spectrum after column fwd+mask+inv, row-major [b][h][w] (w in bitrev-storage order).
__device__ float2 g_scratch2[(size_t)NB * HW * HW];
// Pre-permuted cluster ids: cidP[wp*256+m] = cid[rev8(m)^128][rev8(wp)^128], -1 if unassigned.
__device__ int g_cidP[HW * HW];

__device__ __forceinline__ float2 cmul(float2 a, float2 b) {
    return make_float2(a.x * b.x - a.y * b.y, a.x * b.y + a.y * b.x);
}
__device__ __forceinline__ float2 cmulc(float2 a, float2 b) {  // a * conj(b)
    return make_float2(a.x * b.x + a.y * b.y, a.y * b.x - a.x * b.y);
}

struct Tw {
    float2 T0[4];
    float2 W2, W2i, W4;
    float2 C16, C8, C4, C2;
    float sg16, sg8, sg4, sg2, sg1;
};

__device__ __forceinline__ void make_tw(Tw& t, int l) {
    float s, c;
    sincospif(-(float)l * (1.0f / 128.0f), &s, &c);      // W_256^l
    float2 Wl = make_float2(c, s);
    const float s2 = 0.70710678118654752440f;
    t.T0[0] = Wl;
    t.T0[1] = make_float2(s2 * (Wl.x + Wl.y), s2 * (Wl.y - Wl.x));
    t.T0[2] = make_float2(Wl.y, -Wl.x);
    t.T0[3] = make_float2(s2 * (Wl.y - Wl.x), -s2 * (Wl.x + Wl.y));
    t.W2  = cmul(Wl, Wl);
    t.W2i = make_float2(t.W2.y, -t.W2.x);
    t.W4  = cmul(t.W2, t.W2);
    if (l & 16) { sincospif(-(float)(l & 15) * (1.0f / 16.0f), &s, &c); t.C16 = make_float2(c, s); }
    else t.C16 = make_float2(1.f, 0.f);
    if (l & 8)  { sincospif(-(float)(l & 7) * (1.0f / 8.0f), &s, &c);  t.C8 = make_float2(c, s); }
    else t.C8 = make_float2(1.f, 0.f);
    if (l & 4)  { sincospif(-(float)(l & 3) * (1.0f / 4.0f), &s, &c);  t.C4 = make_float2(c, s); }
    else t.C4 = make_float2(1.f, 0.f);
    t.C2 = ((l & 3) == 3) ? make_float2(0.f, -1.f) : make_float2(1.f, 0.f);
    t.sg16 = (l & 16) ? -1.f : 1.f;
    t.sg8  = (l & 8)  ? -1.f : 1.f;
    t.sg4  = (l & 4)  ? -1.f : 1.f;
    t.sg2  = (l & 2)  ? -1.f : 1.f;
    t.sg1  = (l & 1)  ? -1.f : 1.f;
}

#define BF_F(A, B, W) do { float2 _a = (A), _b = (B); \
    (A) = make_float2(_a.x + _b.x, _a.y + _b.y); \
    (B) = cmul(make_float2(_a.x - _b.x, _a.y - _b.y), (W)); } while (0)
#define BF_I(A, B, W) do { float2 _t = cmulc((B), (W)); float2 _a = (A); \
    (A) = make_float2(_a.x + _t.x, _a.y + _t.y); \
    (B) = make_float2(_a.x - _t.x, _a.y - _t.y); } while (0)

__device__ __forceinline__ void cross_f(float2 r[8], int S, float sg, float2 C) {
#pragma unroll
    for (int k = 0; k < 8; ++k) {
        float vx = __shfl_xor_sync(FULLM, r[k].x, S);
        float vy = __shfl_xor_sync(FULLM, r[k].y, S);
        float2 u = make_float2(fmaf(sg, r[k].x, vx), fmaf(sg, r[k].y, vy));
        r[k] = cmul(u, C);
    }
}
__device__ __forceinline__ void cross_i(float2 r[8], int S, float sg, float2 C) {
#pragma unroll
    for (int k = 0; k < 8; ++k) {
        float2 y = cmulc(r[k], C);
        float vx = __shfl_xor_sync(FULLM, y.x, S);
        float vy = __shfl_xor_sync(FULLM, y.y, S);
        r[k] = make_float2(fmaf(sg, y.x, vx), fmaf(sg, y.y, vy));
    }
}

// Forward DIF FFT-256: natural in (reg k, lane l = idx 32k+l) -> bit-reversed bins in-place.
__device__ __forceinline__ void fwd256(float2 r[8], const Tw& t) {
#pragma unroll
    for (int k = 0; k < 4; ++k) BF_F(r[k], r[k + 4], t.T0[k]);
    BF_F(r[0], r[2], t.W2);  BF_F(r[1], r[3], t.W2i);
    BF_F(r[4], r[6], t.W2);  BF_F(r[5], r[7], t.W2i);
    BF_F(r[0], r[1], t.W4);  BF_F(r[2], r[3], t.W4);
    BF_F(r[4], r[5], t.W4);  BF_F(r[6], r[7], t.W4);
    cross_f(r, 16, t.sg16, t.C16);
    cross_f(r, 8,  t.sg8,  t.C8);
    cross_f(r, 4,  t.sg4,  t.C4);
    cross_f(r, 2,  t.sg2,  t.C2);
#pragma unroll
    for (int k = 0; k < 8; ++k) {
        float vx = __shfl_xor_sync(FULLM, r[k].x, 1);
        float vy = __shfl_xor_sync(FULLM, r[k].y, 1);
        r[k] = make_float2(fmaf(t.sg1, r[k].x, vx), fmaf(t.sg1, r[k].y, vy));
    }
}

// Inverse (unnormalized, x256) DIT FFT-256: bit-reversed bins in -> natural out.
__device__ __forceinline__ void inv256(float2 r[8], const Tw& t) {
#pragma unroll
    for (int k = 0; k < 8; ++k) {
        float vx = __shfl_xor_sync(FULLM, r[k].x, 1);
        float vy = __shfl_xor_sync(FULLM, r[k].y, 1);
        r[k] = make_float2(fmaf(t.sg1, r[k].x, vx), fmaf(t.sg1, r[k].y, vy));
    }
    cross_i(r, 2,  t.sg2,  t.C2);
    cross_i(r, 4,  t.sg4,  t.C4);
    cross_i(r, 8,  t.sg8,  t.C8);
    cross_i(r, 16, t.sg16, t.C16);
    BF_I(r[0], r[1], t.W4);  BF_I(r[2], r[3], t.W4);
    BF_I(r[4], r[5], t.W4);  BF_I(r[6], r[7], t.W4);
    BF_I(r[0], r[2], t.W2);  BF_I(r[1], r[3], t.W2i);
    BF_I(r[4], r[6], t.W2);  BF_I(r[5], r[7], t.W2i);
#pragma unroll
    for (int k = 0; k < 4; ++k) BF_I(r[k], r[k + 4], t.T0[k]);
}

// Prep: pre-permute cluster map into the k2 access order.
__global__ void k_prep(const int* __restrict__ cid) {
    int idx = blockIdx.x * NTHREADS + threadIdx.x;
    int wp = idx >> 8, m = idx & 255;
    int hs = (__brev(m)  >> 24) ^ 128;
    int ws = (__brev(wp) >> 24) ^ 128;
    int c = cid[hs * HW + ws];
    g_cidP[idx] = (c < NCLUST) ? c : -1;
}

// Kernel 1: row forward FFT (register/shuffle), write scratch transposed [b][w][h].
__global__ void k_rowfft(const float* __restrict__ x) {
    extern __shared__ float2 tile[];     // [32][PAD2]
    int tid = threadIdx.x, lane = tid & 31, warp = tid >> 5;
    int b = blockIdx.x >> 3, h0 = (blockIdx.x & 7) << 5;
    Tw t; make_tw(t, lane);
#pragma unroll
    for (int rr = 0; rr < 4; ++rr) {
        int row = warp * 4 + rr;
        const float* xr = x + (size_t)(b * HW + h0 + row) * HW;
        float2 r[8];
#pragma unroll
        for (int k = 0; k < 8; ++k) r[k] = make_float2(xr[32 * k + lane], 0.f);
        fwd256(r, t);
        float2* trow = tile + row * PAD2;
#pragma unroll
        for (int k = 0; k < 8; ++k) trow[32 * k + lane] = r[k];
    }
    __syncthreads();
    float2* sb = g_scratch + (size_t)b * HW * HW + h0;
    for (int idx = tid; idx < 32 * HW; idx += NTHREADS) {
        int rr = idx & 31, w = idx >> 5;             // 256B coalesced global chunks
        sb[(size_t)w * HW + rr] = tile[rr * PAD2 + w];
    }
}

// Kernel 2: column fwd FFT + mask + column inv FFT; transpose-write to scratch2 [b][h][w].
__global__ void k_colfft_mask(const float* __restrict__ pi) {
    extern __shared__ float2 tile[];     // [32][PAD2], indexed [w_local][h]
    __shared__ float spi[NCLUST];
    int tid = threadIdx.x, lane = tid & 31, warp = tid >> 5;
    int b = blockIdx.x >> 3, wp0 = (blockIdx.x & 7) << 5;
    if (tid < NCLUST) spi[tid] = pi[(b ^ 64) * NCLUST + tid];   // batch fftshift
    Tw t; make_tw(t, lane);
    __syncthreads();
#pragma unroll
    for (int rr = 0; rr < 4; ++rr) {
        int wl = warp * 4 + rr;
        int wp = wp0 + wl;
        const float2* line = g_scratch + (size_t)(b * HW + wp) * HW;
        const int* cp = g_cidP + wp * HW;
        float2 r[8];
#pragma unroll
        for (int k = 0; k < 8; ++k) r[k] = line[32 * k + lane];
        fwd256(r, t);
#pragma unroll
        for (int k = 0; k < 8; ++k) {
            int c = __ldg(&cp[32 * k + lane]);
            float m = (c >= 0) ? spi[c] : 1.0f;
            r[k].x *= m; r[k].y *= m;
        }
        inv256(r, t);
        float2* trow = tile + wl * PAD2;
#pragma unroll
        for (int k = 0; k < 8; ++k) trow[32 * k + lane] = r[k];
    }
    __syncthreads();
    float2* ob = g_scratch2 + (size_t)b * HW * HW + wp0;
    for (int idx = tid; idx < 32 * HW; idx += NTHREADS) {
        int rr = idx & 31, h = idx >> 5;             // 256B coalesced global chunks
        ob[(size_t)h * HW + rr] = tile[rr * PAD2 + h];
    }
}

// Kernel 3: pure streaming — one warp per image row: reg inverse FFT + outputs. No smem.
__global__ void k_out(const float* __restrict__ x, float* __restrict__ out) {
    int tid = threadIdx.x, lane = tid & 31, warp = tid >> 5;
    int row_id = blockIdx.x * (NTHREADS / 32) + warp;   // 0 .. NB*HW-1
    int b = row_id >> 8, h = row_id & 255;
    Tw t; make_tw(t, lane);
    const float2* line = g_scratch2 + (size_t)row_id * HW;
    float2 r[8];
#pragma unroll
    for (int k = 0; k < 8; ++k) r[k] = line[32 * k + lane];
    inv256(r, t);
    const float inv = 1.0f / 65536.0f;
    const float* xr = x + (size_t)row_id * HW;
    float* o0 = out + ((size_t)(b * 3 + 0) * HW + h) * HW;
    float* o1 = out + ((size_t)(b * 3 + 1) * HW + h) * HW;
    float* o2 = out + ((size_t)(b * 3 + 2) * HW + h) * HW;
#pragma unroll
    for (int k = 0; k < 8; ++k) {
        int idx = 32 * k + lane;
        float2 z = r[k];
        float mag = sqrtf(z.x * z.x + z.y * z.y) * inv;
        float xv = xr[idx];
        o0[idx] = xv;
        o1[idx] = mag;
        o2[idx] = fabsf(mag - xv);
    }
}

#define TILE_BYTES (32 * PAD2 * (int)sizeof(float2))

extern "C" void kernel_launch(void* const* d_in, const int* in_sizes, int n_in,
                              void* d_out, int out_size) {
    (void)in_sizes; (void)n_in;
    const float* x   = (const float*)d_in[0];
    const float* pi  = (const float*)d_in[1];
    const int*   cid = (const int*)d_in[2];
    float* out = (float*)d_out;

    cudaFuncSetAttribute(k_rowfft,      cudaFuncAttributeMaxDynamicSharedMemorySize, TILE_BYTES);
    cudaFuncSetAttribute(k_colfft_mask, cudaFuncAttributeMaxDynamicSharedMemorySize, TILE_BYTES);

    k_prep<<<HW, NTHREADS>>>(cid);
    k_rowfft<<<NB * 8, NTHREADS, TILE_BYTES>>>(x);
    k_colfft_mask<<<NB * 8, NTHREADS, TILE_BYTES>>>(pi);
    k_out<<<NB * HW / (NTHREADS / 32), NTHREADS>>>(x, out);

    // Second tuple element: pattern_importance passthrough, appended after x_new.
    const long long XN = (long long)NB * 3 * HW * HW;
    if ((long long)out_size >= XN + (long long)NB * NCLUST) {
        cudaMemcpyAsync(out + XN, pi, (size_t)NB * NCLUST * sizeof(float),
                        cudaMemcpyDeviceToDevice);
    }
}